// round 2
// baseline (speedup 1.0000x reference)
#include <cuda_runtime.h>

#define S_LEN   2048
#define NBATCH  64
#define DIN     512
#define HDIM    512
#define NCTA    128
#define NTHREADS 256
#define KT      64
#define ASTRIDE 68          // 64 + 4 pad: conflict-free LDS.128 of A rows
#define NROWS   16          // gate rows per CTA (4 units x 4 gates)
#define KTOT    1024        // DIN + HDIM

// Software grid barrier state (persists across graph replays; gen0-relative)
__device__ unsigned g_bar_count = 0;
__device__ unsigned g_bar_gen   = 0;

__device__ __forceinline__ float fast_sigmoid(float x) {
    return 1.0f / (1.0f + __expf(-x));
}
__device__ __forceinline__ float fast_tanh(float x) {
    float ax = fabsf(x);
    float e  = __expf(-2.0f * ax);
    float t  = (1.0f - e) / (1.0f + e);
    return copysignf(t, x);
}

__global__ __launch_bounds__(NTHREADS, 1)
void lstm_persistent(const float* __restrict__ x,
                     const float* __restrict__ Wih,
                     const float* __restrict__ Whh,
                     const float* __restrict__ bih,
                     const float* __restrict__ bhh,
                     float* __restrict__ out)
{
    extern __shared__ float sm[];
    float* Wsm  = sm;                           // [KTOT * NROWS]        64 KB
    float* As   = Wsm + KTOT * NROWS;           // [2][64 * ASTRIDE]     34 KB
    float* gbuf = As + 2 * 64 * ASTRIDE;        // [NROWS * 64]           4 KB
    float* bsm  = gbuf + NROWS * 64;            // [NROWS]

    const int tid = threadIdx.x;
    const int ct  = blockIdx.x;

    // GEMM mapping: thread (b, q) accumulates rows 4q..4q+3 for batch b
    const int b = tid & 63;
    const int q = tid >> 6;

    // Loader mapping: thread covers row lb, float4 columns kc, kc+16, kc+32, kc+48
    const int lb = tid >> 2;
    const int kc = (tid & 3) * 4;

    // Elementwise mapping: thread (eb, eu) owns (batch eb, local unit eu); c in reg
    const int eb = tid >> 2;
    const int eu = tid & 3;
    float c_state = 0.0f;

    // ---- load persistent weight slice into SMEM ----
    // local row r = unit*4 + gate  ->  global W row = gate*HDIM + ct*4 + unit
    for (int idx = tid; idx < NROWS * KTOT; idx += NTHREADS) {
        int r = idx >> 10;          // 0..15
        int k = idx & (KTOT - 1);   // 0..1023
        int unit = r >> 2, gate = r & 3;
        int grow = gate * HDIM + ct * 4 + unit;
        float w = (k < DIN) ? Wih[grow * DIN + k] : Whh[grow * HDIM + (k - DIN)];
        Wsm[k * NROWS + r] = w;
    }
    if (tid < NROWS) {
        int unit = tid >> 2, gate = tid & 3;
        int grow = gate * HDIM + ct * 4 + unit;
        bsm[tid] = bih[grow] + bhh[grow];
    }

    unsigned gen0 = 0;
    if (tid == 0) gen0 = *((volatile unsigned*)&g_bar_gen);

    float* hout = out;
    float* cout = out + (size_t)S_LEN * NBATCH * HDIM;

    __syncthreads();

    for (int t = 0; t < S_LEN; ++t) {
        float acc0 = 0.f, acc1 = 0.f, acc2 = 0.f, acc3 = 0.f;

        const int nTiles = (t == 0) ? 8 : 16;   // t=0: h phase is all zeros
        const float* xbase = x + (size_t)t * NBATCH * DIN;
        const float* hbase = hout + (size_t)(t - 1) * NBATCH * HDIM;  // valid t>0

        float4 ld0, ld1, ld2, ld3;

#define LOADT(TILE) do {                                                  \
            int _ph = (TILE) >> 3;                                        \
            int _kt = ((TILE) & 7) * KT;                                  \
            const float* _p = ((_ph == 0) ? xbase : hbase)                \
                              + (size_t)lb * 512 + _kt + kc;              \
            ld0 = *(const float4*)(_p);                                   \
            ld1 = *(const float4*)(_p + 16);                              \
            ld2 = *(const float4*)(_p + 32);                              \
            ld3 = *(const float4*)(_p + 48);                              \
        } while (0)

        LOADT(0);

        for (int tile = 0; tile < nTiles; ++tile) {
            const int cur = tile & 1;
            {   // stage prefetched tile into SMEM
                float* d = As + cur * (64 * ASTRIDE) + lb * ASTRIDE + kc;
                *(float4*)(d)      = ld0;
                *(float4*)(d + 16) = ld1;
                *(float4*)(d + 32) = ld2;
                *(float4*)(d + 48) = ld3;
            }
            __syncthreads();
            if (tile + 1 < nTiles) LOADT(tile + 1);

            const float* Arow = As + cur * (64 * ASTRIDE) + b * ASTRIDE;
            const float* Wp   = Wsm + (tile * KT) * NROWS + 4 * q;
#pragma unroll
            for (int kk = 0; kk < KT; kk += 4) {
                float4 a4 = *(const float4*)(Arow + kk);
                float4 w;
                w = *(const float4*)(Wp + (kk + 0) * NROWS);
                acc0 += a4.x * w.x; acc1 += a4.x * w.y;
                acc2 += a4.x * w.z; acc3 += a4.x * w.w;
                w = *(const float4*)(Wp + (kk + 1) * NROWS);
                acc0 += a4.y * w.x; acc1 += a4.y * w.y;
                acc2 += a4.y * w.z; acc3 += a4.y * w.w;
                w = *(const float4*)(Wp + (kk + 2) * NROWS);
                acc0 += a4.z * w.x; acc1 += a4.z * w.y;
                acc2 += a4.z * w.z; acc3 += a4.z * w.w;
                w = *(const float4*)(Wp + (kk + 3) * NROWS);
                acc0 += a4.w * w.x; acc1 += a4.w * w.y;
                acc2 += a4.w * w.z; acc3 += a4.w * w.w;
            }
            __syncthreads();
        }
#undef LOADT

        // gates -> SMEM for the elementwise remap
        gbuf[(4 * q + 0) * 64 + b] = acc0 + bsm[4 * q + 0];
        gbuf[(4 * q + 1) * 64 + b] = acc1 + bsm[4 * q + 1];
        gbuf[(4 * q + 2) * 64 + b] = acc2 + bsm[4 * q + 2];
        gbuf[(4 * q + 3) * 64 + b] = acc3 + bsm[4 * q + 3];
        __syncthreads();

        // elementwise LSTM cell: rows eu*4 + {i,f,g,o}
        float gi = fast_sigmoid(gbuf[(eu * 4 + 0) * 64 + eb]);
        float gf = fast_sigmoid(gbuf[(eu * 4 + 1) * 64 + eb]);
        float gg = fast_tanh  (gbuf[(eu * 4 + 2) * 64 + eb]);
        float go = fast_sigmoid(gbuf[(eu * 4 + 3) * 64 + eb]);
        c_state = gf * c_state + gi * gg;
        float hval = go * fast_tanh(c_state);

        size_t o = (size_t)t * NBATCH * HDIM + (size_t)eb * HDIM + ct * 4 + eu;
        hout[o] = hval;
        cout[o] = c_state;

        // ---- grid barrier: h_t must be globally visible before step t+1 ----
        __threadfence();
        __syncthreads();
        if (tid == 0) {
            unsigned target = gen0 + (unsigned)t + 1u;
            unsigned old = atomicAdd(&g_bar_count, 1u);
            if (old == (unsigned)(NCTA - 1)) {
                atomicExch(&g_bar_count, 0u);
                __threadfence();
                atomicAdd(&g_bar_gen, 1u);
            } else {
                while ((int)(*((volatile unsigned*)&g_bar_gen) - target) < 0) { }
            }
        }
        __syncthreads();
    }
}

extern "C" void kernel_launch(void* const* d_in, const int* in_sizes, int n_in,
                              void* d_out, int out_size)
{
    const float* x   = (const float*)d_in[0];
    const float* Wih = (const float*)d_in[1];
    const float* Whh = (const float*)d_in[2];
    const float* bih = (const float*)d_in[3];
    const float* bhh = (const float*)d_in[4];
    float* out = (float*)d_out;

    // 104.5 KB used; request 132 KB to force 1 CTA/SM (guarantees the 128-CTA
    // persistent grid is fully co-resident -> software barrier is deadlock-free
    // and no SM carries two CTAs while others idle).
    const int smem_bytes = 132 * 1024;
    cudaFuncSetAttribute(lstm_persistent,
                         cudaFuncAttributeMaxDynamicSharedMemorySize, smem_bytes);

    lstm_persistent<<<NCTA, NTHREADS, smem_bytes>>>(x, Wih, Whh, bih, bhh, out);
}